// round 1
// baseline (speedup 1.0000x reference)
#include <cuda_runtime.h>
#include <cstdint>
#include <math.h>

static constexpr int B_  = 2;
static constexpr int T_  = 2048;
static constexpr int D_  = 1024;
static constexpr int H_  = 16;
static constexpr int DH_ = 64;
static constexpr int BT  = B_ * T_;    // 4096
static constexpr int HD  = H_ * DH_;   // 1024

// Scratch (allocation-free rule: __device__ globals)
__device__ float g_q[BT * HD];
__device__ float g_k[BT * HD];
__device__ float g_v[BT * HD];
__device__ float g_ctx[BT * HD];

// ---------------------------------------------------------------------------
// SGEMM: C[M,N] = A[M,K] @ B[K,N], all row-major fp32.
// BM=BN=128, BK=8, 256 threads, 8x8 per thread as 2x2 blocks of 4x4 frags.
// Requires M%128==0, N%128==0, K%8==0 (true for all calls here).
// ---------------------------------------------------------------------------
__global__ __launch_bounds__(256) void sgemm128(const float* __restrict__ A,
                                                const float* __restrict__ Bm,
                                                float* __restrict__ C,
                                                int M, int N, int K) {
    __shared__ float As[8][128];   // transposed A tile: As[k][m]
    __shared__ float Bs[8][128];   // Bs[k][n]

    const int tid = threadIdx.x;
    const int bx = blockIdx.x;     // N tile
    const int by = blockIdx.y;     // M tile

    const int trow = tid >> 4;     // 0..15
    const int tcol = tid & 15;     // 0..15

    const int aRow = tid >> 1;             // 0..127
    const int aCol = (tid & 1) * 4;        // 0 or 4
    const int bRow = tid >> 5;             // 0..7
    const int bCol = (tid & 31) * 4;       // 0..124

    const float* Ap = A + (size_t)(by * 128 + aRow) * K + aCol;
    const float* Bp = Bm + (size_t)bRow * N + bx * 128 + bCol;

    float acc[2][2][4][4];
#pragma unroll
    for (int ii = 0; ii < 2; ii++)
#pragma unroll
        for (int jj = 0; jj < 2; jj++)
#pragma unroll
            for (int i = 0; i < 4; i++)
#pragma unroll
                for (int j = 0; j < 4; j++) acc[ii][jj][i][j] = 0.f;

    for (int kt = 0; kt < K; kt += 8) {
        float4 a4 = *(const float4*)(Ap + kt);
        float4 b4 = *(const float4*)(Bp + (size_t)kt * N);
        As[aCol + 0][aRow] = a4.x;
        As[aCol + 1][aRow] = a4.y;
        As[aCol + 2][aRow] = a4.z;
        As[aCol + 3][aRow] = a4.w;
        *(float4*)&Bs[bRow][bCol] = b4;
        __syncthreads();

#pragma unroll
        for (int k = 0; k < 8; k++) {
            float4 a0 = *(const float4*)&As[k][trow * 4];
            float4 a1 = *(const float4*)&As[k][64 + trow * 4];
            float4 b0 = *(const float4*)&Bs[k][tcol * 4];
            float4 b1 = *(const float4*)&Bs[k][64 + tcol * 4];
            float av[2][4] = {{a0.x, a0.y, a0.z, a0.w}, {a1.x, a1.y, a1.z, a1.w}};
            float bv[2][4] = {{b0.x, b0.y, b0.z, b0.w}, {b1.x, b1.y, b1.z, b1.w}};
#pragma unroll
            for (int ii = 0; ii < 2; ii++)
#pragma unroll
                for (int jj = 0; jj < 2; jj++)
#pragma unroll
                    for (int i = 0; i < 4; i++)
#pragma unroll
                        for (int j = 0; j < 4; j++)
                            acc[ii][jj][i][j] = fmaf(av[ii][i], bv[jj][j], acc[ii][jj][i][j]);
        }
        __syncthreads();
    }

#pragma unroll
    for (int ii = 0; ii < 2; ii++)
#pragma unroll
        for (int i = 0; i < 4; i++) {
            int r = by * 128 + ii * 64 + trow * 4 + i;
#pragma unroll
            for (int jj = 0; jj < 2; jj++) {
                int c = bx * 128 + jj * 64 + tcol * 4;
                float4 v4 = make_float4(acc[ii][jj][i][0], acc[ii][jj][i][1],
                                        acc[ii][jj][i][2], acc[ii][jj][i][3]);
                *(float4*)&C[(size_t)r * N + c] = v4;
            }
        }
}

// ---------------------------------------------------------------------------
// Fused flash attention (fp32, online softmax).
// grid (T/64, H, B), 256 threads. Thread owns one q-row (tid&63) and a
// 16-wide segment (tid>>6) of key-cols / output-dims.
// K smem tile is reused as the P (probability) tile.
// ---------------------------------------------------------------------------
__global__ __launch_bounds__(256) void attn_kernel(const float* __restrict__ Q,
                                                   const float* __restrict__ K,
                                                   const float* __restrict__ V,
                                                   const int* __restrict__ mask,
                                                   float* __restrict__ Ctx) {
    extern __shared__ float sm[];
    float* Qs = sm;               // [64][65]  (pad 65: conflict-free row-varying access)
    float* Ks = sm + 64 * 65;     // [64][65]  (reused as P)
    float* Vs = sm + 2 * 64 * 65; // [64][64]  (broadcast reads only -> no pad)
    __shared__ float red_m[4][64];
    __shared__ float red_s[4][64];
    __shared__ float bias_s[64];

    const int qt = blockIdx.x, h = blockIdx.y, b = blockIdx.z;
    const int tid = threadIdx.x;
    const int row = tid & 63;
    const int seg = tid >> 6;
    const int c0 = seg * 16;

    const size_t qbase = ((size_t)(b * T_) + qt * 64) * HD + h * DH_;
    for (int i = tid; i < 64 * 64; i += 256) {
        int r = i >> 6, d = i & 63;
        Qs[r * 65 + d] = Q[qbase + (size_t)r * HD + d];
    }

    float m = -INFINITY, l = 0.f;
    float o[16];
#pragma unroll
    for (int j = 0; j < 16; j++) o[j] = 0.f;

    for (int kt = 0; kt < T_; kt += 64) {
        __syncthreads();  // guards Qs (first iter) / prior P+V reads before overwrite
        const size_t kbase = ((size_t)(b * T_) + kt) * HD + h * DH_;
        for (int i = tid; i < 64 * 64; i += 256) {
            int r = i >> 6, d = i & 63;
            Ks[r * 65 + d] = K[kbase + (size_t)r * HD + d];
            Vs[r * 64 + d] = V[kbase + (size_t)r * HD + d];
        }
        if (tid < 64)
            bias_s[tid] = (1.0f - (float)mask[b * T_ + kt + tid]) * -1e9f;
        __syncthreads();

        // S = Q K^T for my (row, 16 cols)
        float s[16];
#pragma unroll
        for (int j = 0; j < 16; j++) s[j] = 0.f;
#pragma unroll 4
        for (int k = 0; k < 64; k++) {
            float qv = Qs[row * 65 + k];
#pragma unroll
            for (int j = 0; j < 16; j++)
                s[j] = fmaf(qv, Ks[(c0 + j) * 65 + k], s[j]);
        }

        float tmax = -INFINITY;
#pragma unroll
        for (int j = 0; j < 16; j++) {
            s[j] = s[j] * 0.125f + bias_s[c0 + j];  // scale = Dh^-0.5 = 1/8
            tmax = fmaxf(tmax, s[j]);
        }
        red_m[seg][row] = tmax;
        __syncthreads();  // also guarantees all s computed before Ks overwritten by P

        float nm = fmaxf(m, fmaxf(fmaxf(red_m[0][row], red_m[1][row]),
                                  fmaxf(red_m[2][row], red_m[3][row])));
        float alpha = __expf(m - nm);  // m=-inf first iter -> 0
        m = nm;

        float psum = 0.f;
#pragma unroll
        for (int j = 0; j < 16; j++) {
            float p = __expf(s[j] - nm);
            psum += p;
            Ks[row * 65 + c0 + j] = p;  // P overwrites K tile
        }
        red_s[seg][row] = psum;
#pragma unroll
        for (int j = 0; j < 16; j++) o[j] *= alpha;
        __syncthreads();

        l = l * alpha + red_s[0][row] + red_s[1][row] + red_s[2][row] + red_s[3][row];

        // O += P @ V for my (row, 16 dims)
#pragma unroll 4
        for (int c = 0; c < 64; c++) {
            float p = Ks[row * 65 + c];
#pragma unroll
            for (int j = 0; j < 16; j++)
                o[j] = fmaf(p, Vs[c * 64 + c0 + j], o[j]);
        }
    }

    float inv = 1.f / l;
    const size_t obase = ((size_t)(b * T_) + qt * 64 + row) * HD + h * DH_ + c0;
#pragma unroll
    for (int j = 0; j < 16; j++) Ctx[obase + j] = o[j] * inv;
}

// ---------------------------------------------------------------------------
// kernel_launch: x @ Wq/Wk/Wv -> flash attention -> ctx @ Wo
// Inputs: [0]=x f32, [1]=attention_mask i32, [2]=Wq, [3]=Wk, [4]=Wv, [5]=Wo
// ---------------------------------------------------------------------------
extern "C" void kernel_launch(void* const* d_in, const int* in_sizes, int n_in,
                              void* d_out, int out_size) {
    const float* x    = (const float*)d_in[0];
    const int*   mask = (const int*)d_in[1];
    const float* Wq   = (const float*)d_in[2];
    const float* Wk   = (const float*)d_in[3];
    const float* Wv   = (const float*)d_in[4];
    const float* Wo   = (const float*)d_in[5];
    float* out = (float*)d_out;

    float *q, *k, *v, *ctx;
    cudaGetSymbolAddress((void**)&q, g_q);
    cudaGetSymbolAddress((void**)&k, g_k);
    cudaGetSymbolAddress((void**)&v, g_v);
    cudaGetSymbolAddress((void**)&ctx, g_ctx);

    dim3 gg(HD / 128, BT / 128);  // (8, 32)
    sgemm128<<<gg, 256>>>(x, Wq, q, BT, HD, D_);
    sgemm128<<<gg, 256>>>(x, Wk, k, BT, HD, D_);
    sgemm128<<<gg, 256>>>(x, Wv, v, BT, HD, D_);

    size_t smem = (size_t)(2 * 64 * 65 + 64 * 64) * sizeof(float);  // 49,664 B
    cudaFuncSetAttribute(attn_kernel, cudaFuncAttributeMaxDynamicSharedMemorySize,
                         (int)smem);
    attn_kernel<<<dim3(T_ / 64, H_, B_), 256, smem>>>(q, k, v, mask, ctx);

    sgemm128<<<gg, 256>>>(ctx, Wo, out, BT, HD, HD);
}

// round 2
// speedup vs baseline: 1.2692x; 1.2692x over previous
#include <cuda_runtime.h>
#include <cstdint>
#include <math.h>

static constexpr int B_  = 2;
static constexpr int T_  = 2048;
static constexpr int D_  = 1024;
static constexpr int H_  = 16;
static constexpr int DH_ = 64;
static constexpr int BT  = B_ * T_;    // 4096
static constexpr int HD  = H_ * DH_;   // 1024

// Scratch (allocation-free rule: __device__ globals)
__device__ float g_q[BT * HD];
__device__ float g_k[BT * HD];
__device__ float g_v[BT * HD];
__device__ float g_ctx[BT * HD];

// ---------------------------------------------------------------------------
// SGEMM: C[M,N] = A[M,K] @ B[K,N], all row-major fp32.
// BM=BN=128, BK=8, 256 threads, 8x8 per thread as 2x2 blocks of 4x4 frags.
// ---------------------------------------------------------------------------
__global__ __launch_bounds__(256) void sgemm128(const float* __restrict__ A,
                                                const float* __restrict__ Bm,
                                                float* __restrict__ C,
                                                int M, int N, int K) {
    __shared__ float As[8][128];   // transposed A tile: As[k][m]
    __shared__ float Bs[8][128];   // Bs[k][n]

    const int tid = threadIdx.x;
    const int bx = blockIdx.x;     // N tile
    const int by = blockIdx.y;     // M tile

    const int trow = tid >> 4;     // 0..15
    const int tcol = tid & 15;     // 0..15

    const int aRow = tid >> 1;             // 0..127
    const int aCol = (tid & 1) * 4;        // 0 or 4
    const int bRow = tid >> 5;             // 0..7
    const int bCol = (tid & 31) * 4;       // 0..124

    const float* Ap = A + (size_t)(by * 128 + aRow) * K + aCol;
    const float* Bp = Bm + (size_t)bRow * N + bx * 128 + bCol;

    float acc[2][2][4][4];
#pragma unroll
    for (int ii = 0; ii < 2; ii++)
#pragma unroll
        for (int jj = 0; jj < 2; jj++)
#pragma unroll
            for (int i = 0; i < 4; i++)
#pragma unroll
                for (int j = 0; j < 4; j++) acc[ii][jj][i][j] = 0.f;

    for (int kt = 0; kt < K; kt += 8) {
        float4 a4 = *(const float4*)(Ap + kt);
        float4 b4 = *(const float4*)(Bp + (size_t)kt * N);
        As[aCol + 0][aRow] = a4.x;
        As[aCol + 1][aRow] = a4.y;
        As[aCol + 2][aRow] = a4.z;
        As[aCol + 3][aRow] = a4.w;
        *(float4*)&Bs[bRow][bCol] = b4;
        __syncthreads();

#pragma unroll
        for (int k = 0; k < 8; k++) {
            float4 a0 = *(const float4*)&As[k][trow * 4];
            float4 a1 = *(const float4*)&As[k][64 + trow * 4];
            float4 b0 = *(const float4*)&Bs[k][tcol * 4];
            float4 b1 = *(const float4*)&Bs[k][64 + tcol * 4];
            float av[2][4] = {{a0.x, a0.y, a0.z, a0.w}, {a1.x, a1.y, a1.z, a1.w}};
            float bv[2][4] = {{b0.x, b0.y, b0.z, b0.w}, {b1.x, b1.y, b1.z, b1.w}};
#pragma unroll
            for (int ii = 0; ii < 2; ii++)
#pragma unroll
                for (int jj = 0; jj < 2; jj++)
#pragma unroll
                    for (int i = 0; i < 4; i++)
#pragma unroll
                        for (int j = 0; j < 4; j++)
                            acc[ii][jj][i][j] = fmaf(av[ii][i], bv[jj][j], acc[ii][jj][i][j]);
        }
        __syncthreads();
    }

#pragma unroll
    for (int ii = 0; ii < 2; ii++)
#pragma unroll
        for (int i = 0; i < 4; i++) {
            int r = by * 128 + ii * 64 + trow * 4 + i;
#pragma unroll
            for (int jj = 0; jj < 2; jj++) {
                int c = bx * 128 + jj * 64 + tcol * 4;
                float4 v4 = make_float4(acc[ii][jj][i][0], acc[ii][jj][i][1],
                                        acc[ii][jj][i][2], acc[ii][jj][i][3]);
                *(float4*)&C[(size_t)r * N + c] = v4;
            }
        }
}

// ---------------------------------------------------------------------------
// Fused flash attention (fp32, online softmax), register-tiled.
// grid (T/64, H, B), 256 threads as 16x16; each thread owns a 4x4 fragment.
// S phase: rows cyclic trow+16i, cols cyclic tcol+16j (shfl reductions stay in
//          16-lane groups). PV phase: rows cyclic, dims blocked tcol*4+j.
// All inner-loop smem traffic is float4 (pad 68 keeps alignment & <=2-way
// conflicts). K smem tile reused as the P tile.
// ---------------------------------------------------------------------------
static constexpr int QP = 68;  // padded row stride for Q/K tiles

__global__ __launch_bounds__(256) void attn_kernel(const float* __restrict__ Q,
                                                   const float* __restrict__ K,
                                                   const float* __restrict__ V,
                                                   const int* __restrict__ mask,
                                                   float* __restrict__ Ctx) {
    extern __shared__ float sm[];
    float* Qs = sm;                // [64][68]
    float* Ks = sm + 64 * QP;      // [64][68]  (reused as P)
    float* Vs = sm + 2 * 64 * QP;  // [64][64]
    __shared__ float bias_s[64];

    const int qt = blockIdx.x, h = blockIdx.y, b = blockIdx.z;
    const int tid = threadIdx.x;
    const int trow = tid >> 4;   // 0..15
    const int tcol = tid & 15;   // 0..15

    const size_t qbase = ((size_t)(b * T_) + qt * 64) * HD + h * DH_;
#pragma unroll
    for (int it = 0; it < 4; it++) {
        int i = tid + it * 256;          // 0..1023 float4 slots
        int r = i >> 4, d0 = (i & 15) * 4;
        *(float4*)&Qs[r * QP + d0] = *(const float4*)(Q + qbase + (size_t)r * HD + d0);
    }

    float m[4], l[4], o[4][4];
#pragma unroll
    for (int i = 0; i < 4; i++) {
        m[i] = -INFINITY; l[i] = 0.f;
#pragma unroll
        for (int j = 0; j < 4; j++) o[i][j] = 0.f;
    }

    for (int kt = 0; kt < T_; kt += 64) {
        __syncthreads();  // prior tile's P/V reads done; Qs ready (first iter)
        const size_t kbase = ((size_t)(b * T_) + kt) * HD + h * DH_;
#pragma unroll
        for (int it = 0; it < 4; it++) {
            int i = tid + it * 256;
            int r = i >> 4, d0 = (i & 15) * 4;
            *(float4*)&Ks[r * QP + d0] = *(const float4*)(K + kbase + (size_t)r * HD + d0);
            *(float4*)&Vs[r * 64 + d0] = *(const float4*)(V + kbase + (size_t)r * HD + d0);
        }
        if (tid < 64)
            bias_s[tid] = (1.0f - (float)mask[b * T_ + kt + tid]) * -1e9f;
        __syncthreads();

        // ---- S = Q K^T : 4x4 fragment, float4 along k ----
        float s[4][4];
#pragma unroll
        for (int i = 0; i < 4; i++)
#pragma unroll
            for (int j = 0; j < 4; j++) s[i][j] = 0.f;

#pragma unroll
        for (int k = 0; k < 64; k += 4) {
            float4 qv[4], kv[4];
#pragma unroll
            for (int i = 0; i < 4; i++)
                qv[i] = *(const float4*)&Qs[(trow + 16 * i) * QP + k];
#pragma unroll
            for (int j = 0; j < 4; j++)
                kv[j] = *(const float4*)&Ks[(tcol + 16 * j) * QP + k];
#pragma unroll
            for (int i = 0; i < 4; i++)
#pragma unroll
                for (int j = 0; j < 4; j++) {
                    s[i][j] = fmaf(qv[i].x, kv[j].x, s[i][j]);
                    s[i][j] = fmaf(qv[i].y, kv[j].y, s[i][j]);
                    s[i][j] = fmaf(qv[i].z, kv[j].z, s[i][j]);
                    s[i][j] = fmaf(qv[i].w, kv[j].w, s[i][j]);
                }
        }

        // ---- online softmax (per-row; 16-lane shfl reductions) ----
        float bj[4];
#pragma unroll
        for (int j = 0; j < 4; j++) bj[j] = bias_s[tcol + 16 * j];

#pragma unroll
        for (int i = 0; i < 4; i++) {
            float tm = -INFINITY;
#pragma unroll
            for (int j = 0; j < 4; j++) {
                s[i][j] = fmaf(s[i][j], 0.125f, bj[j]);  // scale = Dh^-0.5
                tm = fmaxf(tm, s[i][j]);
            }
#pragma unroll
            for (int off = 8; off >= 1; off >>= 1)
                tm = fmaxf(tm, __shfl_xor_sync(0xffffffffu, tm, off));
            float nm = fmaxf(m[i], tm);
            float alpha = __expf(m[i] - nm);  // m=-inf first tile -> 0
            m[i] = nm;
            float ps = 0.f;
#pragma unroll
            for (int j = 0; j < 4; j++) {
                s[i][j] = __expf(s[i][j] - nm);  // s becomes P
                ps += s[i][j];
            }
#pragma unroll
            for (int off = 8; off >= 1; off >>= 1)
                ps += __shfl_xor_sync(0xffffffffu, ps, off);
            l[i] = l[i] * alpha + ps;
#pragma unroll
            for (int j = 0; j < 4; j++) o[i][j] *= alpha;
        }
        __syncthreads();  // everyone done reading Ks before P overwrite

#pragma unroll
        for (int i = 0; i < 4; i++)
#pragma unroll
            for (int j = 0; j < 4; j++)
                Ks[(trow + 16 * i) * QP + tcol + 16 * j] = s[i][j];
        __syncthreads();

        // ---- O += P @ V : rows cyclic, dims blocked (tcol*4+j) ----
#pragma unroll
        for (int c = 0; c < 64; c += 4) {
            float4 pv[4], vv[4];
#pragma unroll
            for (int i = 0; i < 4; i++)
                pv[i] = *(const float4*)&Ks[(trow + 16 * i) * QP + c];
#pragma unroll
            for (int cc = 0; cc < 4; cc++)
                vv[cc] = *(const float4*)&Vs[(c + cc) * 64 + tcol * 4];
#pragma unroll
            for (int i = 0; i < 4; i++) {
                o[i][0] = fmaf(pv[i].x, vv[0].x, o[i][0]);
                o[i][1] = fmaf(pv[i].x, vv[0].y, o[i][1]);
                o[i][2] = fmaf(pv[i].x, vv[0].z, o[i][2]);
                o[i][3] = fmaf(pv[i].x, vv[0].w, o[i][3]);
                o[i][0] = fmaf(pv[i].y, vv[1].x, o[i][0]);
                o[i][1] = fmaf(pv[i].y, vv[1].y, o[i][1]);
                o[i][2] = fmaf(pv[i].y, vv[1].z, o[i][2]);
                o[i][3] = fmaf(pv[i].y, vv[1].w, o[i][3]);
                o[i][0] = fmaf(pv[i].z, vv[2].x, o[i][0]);
                o[i][1] = fmaf(pv[i].z, vv[2].y, o[i][1]);
                o[i][2] = fmaf(pv[i].z, vv[2].z, o[i][2]);
                o[i][3] = fmaf(pv[i].z, vv[2].w, o[i][3]);
                o[i][0] = fmaf(pv[i].w, vv[3].x, o[i][0]);
                o[i][1] = fmaf(pv[i].w, vv[3].y, o[i][1]);
                o[i][2] = fmaf(pv[i].w, vv[3].z, o[i][2]);
                o[i][3] = fmaf(pv[i].w, vv[3].w, o[i][3]);
            }
        }
    }

    // ---- epilogue: normalize + write (float4, coalesced) ----
#pragma unroll
    for (int i = 0; i < 4; i++) {
        int r = trow + 16 * i;
        float inv = 1.f / l[i];
        float4 w = make_float4(o[i][0] * inv, o[i][1] * inv,
                               o[i][2] * inv, o[i][3] * inv);
        *(float4*)&Ctx[qbase + (size_t)r * HD + tcol * 4] = w;
    }
}

// ---------------------------------------------------------------------------
// kernel_launch: x @ Wq/Wk/Wv -> flash attention -> ctx @ Wo
// Inputs: [0]=x f32, [1]=attention_mask i32, [2]=Wq, [3]=Wk, [4]=Wv, [5]=Wo
// ---------------------------------------------------------------------------
extern "C" void kernel_launch(void* const* d_in, const int* in_sizes, int n_in,
                              void* d_out, int out_size) {
    const float* x    = (const float*)d_in[0];
    const int*   mask = (const int*)d_in[1];
    const float* Wq   = (const float*)d_in[2];
    const float* Wk   = (const float*)d_in[3];
    const float* Wv   = (const float*)d_in[4];
    const float* Wo   = (const float*)d_in[5];
    float* out = (float*)d_out;

    float *q, *k, *v, *ctx;
    cudaGetSymbolAddress((void**)&q, g_q);
    cudaGetSymbolAddress((void**)&k, g_k);
    cudaGetSymbolAddress((void**)&v, g_v);
    cudaGetSymbolAddress((void**)&ctx, g_ctx);

    dim3 gg(HD / 128, BT / 128);  // (8, 32)
    sgemm128<<<gg, 256>>>(x, Wq, q, BT, HD, D_);
    sgemm128<<<gg, 256>>>(x, Wk, k, BT, HD, D_);
    sgemm128<<<gg, 256>>>(x, Wv, v, BT, HD, D_);

    size_t smem = (size_t)(2 * 64 * QP + 64 * 64) * sizeof(float);  // 51,200 B
    cudaFuncSetAttribute(attn_kernel, cudaFuncAttributeMaxDynamicSharedMemorySize,
                         (int)smem);
    attn_kernel<<<dim3(T_ / 64, H_, B_), 256, smem>>>(q, k, v, mask, ctx);

    sgemm128<<<gg, 256>>>(ctx, Wo, out, BT, HD, HD);
}

// round 4
// speedup vs baseline: 2.0940x; 1.6498x over previous
#include <cuda_runtime.h>
#include <cuda_fp16.h>
#include <cstdint>
#include <math.h>

static constexpr int B_  = 2;
static constexpr int T_  = 2048;
static constexpr int D_  = 1024;
static constexpr int H_  = 16;
static constexpr int DH_ = 64;
static constexpr int BT  = B_ * T_;    // 4096
static constexpr int HD  = H_ * DH_;   // 1024

// Scratch (allocation-free rule: __device__ globals)
__device__ float  g_q[BT * HD];
__device__ float  g_k[BT * HD];
__device__ float  g_v[BT * HD];
__device__ float  g_ctx[BT * HD];
__device__ __half g_x16[BT * D_];
__device__ __half g_ctx16[BT * HD];
__device__ __half g_wqt[D_ * HD];   // [N][K] transposed fp16
__device__ __half g_wkt[D_ * HD];
__device__ __half g_wvt[D_ * HD];
__device__ __half g_wot[HD * D_];

// ===========================================================================
// PTX helpers: mma.sync / ldmatrix / cp.async (arch-neutral, work on sm_103)
// ===========================================================================
__device__ __forceinline__ uint32_t smem_u32(const void* p) {
    uint32_t a;
    asm("{ .reg .u64 t; cvta.to.shared.u64 t, %1; cvt.u32.u64 %0, t; }"
        : "=r"(a) : "l"(p));
    return a;
}
#define CP_ASYNC16(dst, src) \
    asm volatile("cp.async.cg.shared.global [%0], [%1], 16;" :: "r"(dst), "l"(src))
#define CP_COMMIT() asm volatile("cp.async.commit_group;" ::: "memory")
#define CP_WAIT(n)  asm volatile("cp.async.wait_group %0;" :: "n"(n) : "memory")

__device__ __forceinline__ void ldsm_x4(uint32_t* r, uint32_t addr) {
    asm volatile("ldmatrix.sync.aligned.m8n8.x4.shared.b16 {%0,%1,%2,%3}, [%4];"
                 : "=r"(r[0]), "=r"(r[1]), "=r"(r[2]), "=r"(r[3]) : "r"(addr));
}
__device__ __forceinline__ void mma16816(float* c, const uint32_t* a,
                                         const uint32_t* b) {
    asm volatile(
        "mma.sync.aligned.m16n8k16.row.col.f32.f16.f16.f32 "
        "{%0,%1,%2,%3}, {%4,%5,%6,%7}, {%8,%9}, {%0,%1,%2,%3};"
        : "+f"(c[0]), "+f"(c[1]), "+f"(c[2]), "+f"(c[3])
        : "r"(a[0]), "r"(a[1]), "r"(a[2]), "r"(a[3]), "r"(b[0]), "r"(b[1]));
}

// ===========================================================================
// Conversion kernels
// ===========================================================================
__global__ __launch_bounds__(256) void f32_to_f16_vec(const float* __restrict__ in,
                                                      __half* __restrict__ out) {
    int i = blockIdx.x * 256 + threadIdx.x;
    float4 v = ((const float4*)in)[i];
    __half2 a = __floats2half2_rn(v.x, v.y);
    __half2 b = __floats2half2_rn(v.z, v.w);
    ((__half2*)out)[2 * i]     = a;
    ((__half2*)out)[2 * i + 1] = b;
}

// Wt[n][k] = (half)W[k][n], both 1024x1024
__global__ __launch_bounds__(256) void transpose_f32_to_f16(const float* __restrict__ W,
                                                            __half* __restrict__ Wt) {
    __shared__ float t[32][33];
    int bx = blockIdx.x * 32;  // n base
    int by = blockIdx.y * 32;  // k base
    int x = threadIdx.x, y0 = threadIdx.y;  // block (32,8)
#pragma unroll
    for (int yy = y0; yy < 32; yy += 8)
        t[yy][x] = W[(size_t)(by + yy) * 1024 + bx + x];
    __syncthreads();
#pragma unroll
    for (int yy = y0; yy < 32; yy += 8)
        Wt[(size_t)(bx + yy) * 1024 + by + x] = __float2half_rn(t[x][yy]);
}

// ===========================================================================
// HMMA fp16 GEMM: C[4096,1024](f32) = A16[4096,K] @ B16t[1024,K]^T
// (B16t is [N][K] row-major = col-major B operand). CTA tile 128x128, BK=32,
// 8 warps (2x4), warp tile 64x32, mma.sync m16n8k16, cp.async double buffer.
// Smem rows padded to 40 halves (80B) -> conflict-free ldmatrix.
// ===========================================================================
static constexpr int GK      = 1024;
static constexpr int LDT     = 40;             // halves per smem row
static constexpr int TILE_B  = 128 * LDT * 2;  // 10240 bytes per tile
static constexpr int BUF_B   = 2 * TILE_B;     // A+B per buffer

__global__ __launch_bounds__(256) void gemm_f16_mma(const __half* __restrict__ Ag,
                                                    const __half* __restrict__ Bg,
                                                    float* __restrict__ Cg) {
    __shared__ __align__(16) char smem[2 * BUF_B];  // 40960 B
    const uint32_t sb = smem_u32(smem);
    const int tid = threadIdx.x, wid = tid >> 5, lane = tid & 31;
    const int warp_m = wid >> 2, warp_n = wid & 3;
    const int bx = blockIdx.x, by = blockIdx.y;

    const __half* Ab = Ag + (size_t)(by * 128) * GK;
    const __half* Bb = Bg + (size_t)(bx * 128) * GK;

    // prefetch lanes: thread covers 2 (row,chunk) slots per operand tile
    const int pr0 = tid >> 2, pc0 = (tid & 3);          // slot 0: rows 0..63
    // ldmatrix lane address components
    const uint32_t aLane = (uint32_t)((lane & 15) * (LDT * 2) + (lane >> 4) * 16);
    const uint32_t bLane = (uint32_t)((((lane >> 4) & 1) * 8 + (lane & 7)) * (LDT * 2)
                                      + ((lane >> 3) & 1) * 16);

    auto prefetch = [&](int kt, int buf) {
        const uint32_t base = sb + (uint32_t)buf * BUF_B;
#pragma unroll
        for (int s = 0; s < 2; s++) {
            int row = pr0 + s * 64, ch = pc0;
            uint32_t off = (uint32_t)(row * (LDT * 2) + ch * 16);
            CP_ASYNC16(base + off,
                       (const void*)(Ab + (size_t)row * GK + kt * 32 + ch * 8));
            CP_ASYNC16(base + TILE_B + off,
                       (const void*)(Bb + (size_t)row * GK + kt * 32 + ch * 8));
        }
    };

    float acc[4][4][4];
#pragma unroll
    for (int i = 0; i < 4; i++)
#pragma unroll
        for (int j = 0; j < 4; j++)
#pragma unroll
            for (int r = 0; r < 4; r++) acc[i][j][r] = 0.f;

    prefetch(0, 0);
    CP_COMMIT();

    const int NKT = GK / 32;
    for (int kt = 0; kt < NKT; kt++) {
        const int buf = kt & 1;
        if (kt + 1 < NKT) {
            prefetch(kt + 1, buf ^ 1);
            CP_COMMIT();
            CP_WAIT(1);
        } else {
            CP_WAIT(0);
        }
        __syncthreads();

        const uint32_t abase = sb + (uint32_t)buf * BUF_B + (uint32_t)(warp_m * 64) * (LDT * 2);
        const uint32_t bbase = sb + (uint32_t)buf * BUF_B + TILE_B + (uint32_t)(warp_n * 32) * (LDT * 2);
#pragma unroll
        for (int ks = 0; ks < 2; ks++) {
            uint32_t a[4][4], b[4][2];
#pragma unroll
            for (int mt = 0; mt < 4; mt++)
                ldsm_x4(a[mt], abase + (uint32_t)(mt * 16 * LDT * 2 + ks * 32) + aLane);
#pragma unroll
            for (int np = 0; np < 2; np++) {
                uint32_t r[4];
                ldsm_x4(r, bbase + (uint32_t)(np * 16 * LDT * 2 + ks * 32) + bLane);
                b[2 * np][0] = r[0]; b[2 * np][1] = r[1];
                b[2 * np + 1][0] = r[2]; b[2 * np + 1][1] = r[3];
            }
#pragma unroll
            for (int mt = 0; mt < 4; mt++)
#pragma unroll
                for (int nt = 0; nt < 4; nt++)
                    mma16816(acc[mt][nt], a[mt], b[nt]);
        }
        __syncthreads();
    }

    // epilogue: c frag: rows (lane/4, +8), cols (lane%4)*2
    const int r0 = by * 128 + warp_m * 64 + (lane >> 2);
    const int c0 = bx * 128 + warp_n * 32 + (lane & 3) * 2;
#pragma unroll
    for (int mt = 0; mt < 4; mt++)
#pragma unroll
        for (int nt = 0; nt < 4; nt++) {
            float* p0 = Cg + (size_t)(r0 + mt * 16) * 1024 + c0 + nt * 8;
            *(float2*)p0 = make_float2(acc[mt][nt][0], acc[mt][nt][1]);
            *(float2*)(p0 + 8 * 1024) = make_float2(acc[mt][nt][2], acc[mt][nt][3]);
        }
}

// ===========================================================================
// Fused flash attention (fp32, online softmax), register-tiled. (unchanged)
// ===========================================================================
static constexpr int QP = 68;

__global__ __launch_bounds__(256) void attn_kernel(const float* __restrict__ Q,
                                                   const float* __restrict__ K,
                                                   const float* __restrict__ V,
                                                   const int* __restrict__ mask,
                                                   float* __restrict__ Ctx) {
    extern __shared__ float sm[];
    float* Qs = sm;                // [64][68]
    float* Ks = sm + 64 * QP;      // [64][68]  (reused as P)
    float* Vs = sm + 2 * 64 * QP;  // [64][64]
    __shared__ float bias_s[64];

    const int qt = blockIdx.x, h = blockIdx.y, b = blockIdx.z;
    const int tid = threadIdx.x;
    const int trow = tid >> 4;
    const int tcol = tid & 15;

    const size_t qbase = ((size_t)(b * T_) + qt * 64) * HD + h * DH_;
#pragma unroll
    for (int it = 0; it < 4; it++) {
        int i = tid + it * 256;
        int r = i >> 4, d0 = (i & 15) * 4;
        *(float4*)&Qs[r * QP + d0] = *(const float4*)(Q + qbase + (size_t)r * HD + d0);
    }

    float m[4], l[4], o[4][4];
#pragma unroll
    for (int i = 0; i < 4; i++) {
        m[i] = -INFINITY; l[i] = 0.f;
#pragma unroll
        for (int j = 0; j < 4; j++) o[i][j] = 0.f;
    }

    for (int kt = 0; kt < T_; kt += 64) {
        __syncthreads();
        const size_t kbase = ((size_t)(b * T_) + kt) * HD + h * DH_;
#pragma unroll
        for (int it = 0; it < 4; it++) {
            int i = tid + it * 256;
            int r = i >> 4, d0 = (i & 15) * 4;
            *(float4*)&Ks[r * QP + d0] = *(const float4*)(K + kbase + (size_t)r * HD + d0);
            *(float4*)&Vs[r * 64 + d0] = *(const float4*)(V + kbase + (size_t)r * HD + d0);
        }
        if (tid < 64)
            bias_s[tid] = (1.0f - (float)mask[b * T_ + kt + tid]) * -1e9f;
        __syncthreads();

        float s[4][4];
#pragma unroll
        for (int i = 0; i < 4; i++)
#pragma unroll
            for (int j = 0; j < 4; j++) s[i][j] = 0.f;

#pragma unroll
        for (int k = 0; k < 64; k += 4) {
            float4 qv[4], kv[4];
#pragma unroll
            for (int i = 0; i < 4; i++)
                qv[i] = *(const float4*)&Qs[(trow + 16 * i) * QP + k];
#pragma unroll
            for (int j = 0; j < 4; j++)
                kv[j] = *(const float4*)&Ks[(tcol + 16 * j) * QP + k];
#pragma unroll
            for (int i = 0; i < 4; i++)
#pragma unroll
                for (int j = 0; j < 4; j++) {
                    s[i][j] = fmaf(qv[i].x, kv[j].x, s[i][j]);
                    s[i][j] = fmaf(qv[i].y, kv[j].y, s[i][j]);
                    s[i][j] = fmaf(qv[i].z, kv[j].z, s[i][j]);
                    s[i][j] = fmaf(qv[i].w, kv[j].w, s[i][j]);
                }
        }

        float bj[4];
#pragma unroll
        for (int j = 0; j < 4; j++) bj[j] = bias_s[tcol + 16 * j];

#pragma unroll
        for (int i = 0; i < 4; i++) {
            float tm = -INFINITY;
#pragma unroll
            for (int j = 0; j < 4; j++) {
                s[i][j] = fmaf(s[i][j], 0.125f, bj[j]);
                tm = fmaxf(tm, s[i][j]);
            }
#pragma unroll
            for (int off = 8; off >= 1; off >>= 1)
                tm = fmaxf(tm, __shfl_xor_sync(0xffffffffu, tm, off));
            float nm = fmaxf(m[i], tm);
            float alpha = __expf(m[i] - nm);
            m[i] = nm;
            float ps = 0.f;
#pragma unroll
            for (int j = 0; j < 4; j++) {
                s[i][j] = __expf(s[i][j] - nm);
                ps += s[i][j];
            }
#pragma unroll
            for (int off = 8; off >= 1; off >>= 1)
                ps += __shfl_xor_sync(0xffffffffu, ps, off);
            l[i] = l[i] * alpha + ps;
#pragma unroll
            for (int j = 0; j < 4; j++) o[i][j] *= alpha;
        }
        __syncthreads();

#pragma unroll
        for (int i = 0; i < 4; i++)
#pragma unroll
            for (int j = 0; j < 4; j++)
                Ks[(trow + 16 * i) * QP + tcol + 16 * j] = s[i][j];
        __syncthreads();

#pragma unroll
        for (int c = 0; c < 64; c += 4) {
            float4 pv[4], vv[4];
#pragma unroll
            for (int i = 0; i < 4; i++)
                pv[i] = *(const float4*)&Ks[(trow + 16 * i) * QP + c];
#pragma unroll
            for (int cc = 0; cc < 4; cc++)
                vv[cc] = *(const float4*)&Vs[(c + cc) * 64 + tcol * 4];
#pragma unroll
            for (int i = 0; i < 4; i++) {
                o[i][0] = fmaf(pv[i].x, vv[0].x, o[i][0]);
                o[i][1] = fmaf(pv[i].x, vv[0].y, o[i][1]);
                o[i][2] = fmaf(pv[i].x, vv[0].z, o[i][2]);
                o[i][3] = fmaf(pv[i].x, vv[0].w, o[i][3]);
                o[i][0] = fmaf(pv[i].y, vv[1].x, o[i][0]);
                o[i][1] = fmaf(pv[i].y, vv[1].y, o[i][1]);
                o[i][2] = fmaf(pv[i].y, vv[1].z, o[i][2]);
                o[i][3] = fmaf(pv[i].y, vv[1].w, o[i][3]);
                o[i][0] = fmaf(pv[i].z, vv[2].x, o[i][0]);
                o[i][1] = fmaf(pv[i].z, vv[2].y, o[i][1]);
                o[i][2] = fmaf(pv[i].z, vv[2].z, o[i][2]);
                o[i][3] = fmaf(pv[i].z, vv[2].w, o[i][3]);
                o[i][0] = fmaf(pv[i].w, vv[3].x, o[i][0]);
                o[i][1] = fmaf(pv[i].w, vv[3].y, o[i][1]);
                o[i][2] = fmaf(pv[i].w, vv[3].z, o[i][2]);
                o[i][3] = fmaf(pv[i].w, vv[3].w, o[i][3]);
            }
        }
    }

#pragma unroll
    for (int i = 0; i < 4; i++) {
        int r = trow + 16 * i;
        float inv = 1.f / l[i];
        float4 w = make_float4(o[i][0] * inv, o[i][1] * inv,
                               o[i][2] * inv, o[i][3] * inv);
        *(float4*)&Ctx[qbase + (size_t)r * HD + tcol * 4] = w;
    }
}

// ===========================================================================
// kernel_launch
// Inputs: [0]=x f32, [1]=attention_mask i32, [2]=Wq, [3]=Wk, [4]=Wv, [5]=Wo
// ===========================================================================
extern "C" void kernel_launch(void* const* d_in, const int* in_sizes, int n_in,
                              void* d_out, int out_size) {
    const float* x    = (const float*)d_in[0];
    const int*   mask = (const int*)d_in[1];
    const float* Wq   = (const float*)d_in[2];
    const float* Wk   = (const float*)d_in[3];
    const float* Wv   = (const float*)d_in[4];
    const float* Wo   = (const float*)d_in[5];
    float* out = (float*)d_out;

    float *q, *k, *v, *ctx;
    __half *x16, *ctx16, *wqt, *wkt, *wvt, *wot;
    cudaGetSymbolAddress((void**)&q, g_q);
    cudaGetSymbolAddress((void**)&k, g_k);
    cudaGetSymbolAddress((void**)&v, g_v);
    cudaGetSymbolAddress((void**)&ctx, g_ctx);
    cudaGetSymbolAddress((void**)&x16, g_x16);
    cudaGetSymbolAddress((void**)&ctx16, g_ctx16);
    cudaGetSymbolAddress((void**)&wqt, g_wqt);
    cudaGetSymbolAddress((void**)&wkt, g_wkt);
    cudaGetSymbolAddress((void**)&wvt, g_wvt);
    cudaGetSymbolAddress((void**)&wot, g_wot);

    // ---- convert inputs to fp16 (x) and transposed fp16 weights ----
    f32_to_f16_vec<<<(BT * D_ / 4) / 256, 256>>>(x, x16);
    dim3 tg(32, 32), tb(32, 8);
    transpose_f32_to_f16<<<tg, tb>>>(Wq, wqt);
    transpose_f32_to_f16<<<tg, tb>>>(Wk, wkt);
    transpose_f32_to_f16<<<tg, tb>>>(Wv, wvt);
    transpose_f32_to_f16<<<tg, tb>>>(Wo, wot);

    // ---- projections on tensor cores (mma.sync HMMA) ----
    dim3 gg(HD / 128, BT / 128);  // (8, 32)
    gemm_f16_mma<<<gg, 256>>>(x16, wqt, q);
    gemm_f16_mma<<<gg, 256>>>(x16, wkt, k);
    gemm_f16_mma<<<gg, 256>>>(x16, wvt, v);

    // ---- attention (fp32) ----
    size_t smem = (size_t)(2 * 64 * QP + 64 * 64) * sizeof(float);
    cudaFuncSetAttribute(attn_kernel, cudaFuncAttributeMaxDynamicSharedMemorySize,
                         (int)smem);
    attn_kernel<<<dim3(T_ / 64, H_, B_), 256, smem>>>(q, k, v, mask, ctx);

    // ---- output projection ----
    f32_to_f16_vec<<<(BT * HD / 4) / 256, 256>>>(ctx, ctx16);
    gemm_f16_mma<<<gg, 256>>>(ctx16, wot, out);
}

// round 5
// speedup vs baseline: 4.7887x; 2.2869x over previous
#include <cuda_runtime.h>
#include <cuda_fp16.h>
#include <cstdint>
#include <math.h>

static constexpr int B_  = 2;
static constexpr int T_  = 2048;
static constexpr int D_  = 1024;
static constexpr int H_  = 16;
static constexpr int DH_ = 64;
static constexpr int BT  = B_ * T_;    // 4096
static constexpr int HD  = H_ * DH_;   // 1024

// Scratch (allocation-free rule: __device__ globals)
__device__ __half g_x16[BT * D_];
__device__ __half g_q16[BT * HD];
__device__ __half g_k16[BT * HD];
__device__ __half g_v16[BT * HD];
__device__ __half g_ctx16[BT * HD];
__device__ __half g_wqt[D_ * HD];   // [N][K] transposed fp16
__device__ __half g_wkt[D_ * HD];
__device__ __half g_wvt[D_ * HD];
__device__ __half g_wot[HD * D_];

// ===========================================================================
// PTX helpers: mma.sync / ldmatrix / cp.async (arch-neutral, work on sm_103)
// ===========================================================================
__device__ __forceinline__ uint32_t smem_u32(const void* p) {
    uint32_t a;
    asm("{ .reg .u64 t; cvta.to.shared.u64 t, %1; cvt.u32.u64 %0, t; }"
        : "=r"(a) : "l"(p));
    return a;
}
#define CP_ASYNC16(dst, src) \
    asm volatile("cp.async.cg.shared.global [%0], [%1], 16;" :: "r"(dst), "l"(src))
#define CP_ASYNC4(dst, src) \
    asm volatile("cp.async.ca.shared.global [%0], [%1], 4;" :: "r"(dst), "l"(src))
#define CP_COMMIT() asm volatile("cp.async.commit_group;" ::: "memory")
#define CP_WAIT(n)  asm volatile("cp.async.wait_group %0;" :: "n"(n) : "memory")

__device__ __forceinline__ void ldsm_x4(uint32_t* r, uint32_t addr) {
    asm volatile("ldmatrix.sync.aligned.m8n8.x4.shared.b16 {%0,%1,%2,%3}, [%4];"
                 : "=r"(r[0]), "=r"(r[1]), "=r"(r[2]), "=r"(r[3]) : "r"(addr));
}
__device__ __forceinline__ void ldsm_x4_t(uint32_t* r, uint32_t addr) {
    asm volatile("ldmatrix.sync.aligned.m8n8.x4.trans.shared.b16 {%0,%1,%2,%3}, [%4];"
                 : "=r"(r[0]), "=r"(r[1]), "=r"(r[2]), "=r"(r[3]) : "r"(addr));
}
__device__ __forceinline__ void mma16816(float* c, const uint32_t* a,
                                         const uint32_t* b) {
    asm volatile(
        "mma.sync.aligned.m16n8k16.row.col.f32.f16.f16.f32 "
        "{%0,%1,%2,%3}, {%4,%5,%6,%7}, {%8,%9}, {%0,%1,%2,%3};"
        : "+f"(c[0]), "+f"(c[1]), "+f"(c[2]), "+f"(c[3])
        : "r"(a[0]), "r"(a[1]), "r"(a[2]), "r"(a[3]), "r"(b[0]), "r"(b[1]));
}

__device__ __forceinline__ void store2(float* p, float a, float b) {
    *(float2*)p = make_float2(a, b);
}
__device__ __forceinline__ void store2(__half* p, float a, float b) {
    *(__half2*)p = __floats2half2_rn(a, b);
}

// ===========================================================================
// Conversion kernels
// ===========================================================================
__global__ __launch_bounds__(256) void f32_to_f16_vec(const float* __restrict__ in,
                                                      __half* __restrict__ out) {
    int i = blockIdx.x * 256 + threadIdx.x;
    float4 v = ((const float4*)in)[i];
    ((__half2*)out)[2 * i]     = __floats2half2_rn(v.x, v.y);
    ((__half2*)out)[2 * i + 1] = __floats2half2_rn(v.z, v.w);
}

// Wt[n][k] = (half)W[k][n], both 1024x1024
__global__ __launch_bounds__(256) void transpose_f32_to_f16(const float* __restrict__ W,
                                                            __half* __restrict__ Wt) {
    __shared__ float t[32][33];
    int bx = blockIdx.x * 32;  // n base
    int by = blockIdx.y * 32;  // k base
    int x = threadIdx.x, y0 = threadIdx.y;  // block (32,8)
#pragma unroll
    for (int yy = y0; yy < 32; yy += 8)
        t[yy][x] = W[(size_t)(by + yy) * 1024 + bx + x];
    __syncthreads();
#pragma unroll
    for (int yy = y0; yy < 32; yy += 8)
        Wt[(size_t)(bx + yy) * 1024 + by + x] = __float2half_rn(t[x][yy]);
}

// ===========================================================================
// HMMA fp16 GEMM: C[4096,1024] = A16[4096,K] @ B16t[1024,K]^T  (OutT = f32/f16)
// CTA tile 128x128, BK=32, 8 warps (2x4), warp tile 64x32, cp.async dbl buf.
// ===========================================================================
static constexpr int GK      = 1024;
static constexpr int LDT     = 40;             // halves per smem row
static constexpr int TILE_B  = 128 * LDT * 2;  // 10240 bytes per tile
static constexpr int BUF_B   = 2 * TILE_B;

template <typename OutT>
__global__ __launch_bounds__(256) void gemm_f16_mma(const __half* __restrict__ Ag,
                                                    const __half* __restrict__ Bg,
                                                    OutT* __restrict__ Cg) {
    __shared__ __align__(16) char smem[2 * BUF_B];  // 40960 B
    const uint32_t sb = smem_u32(smem);
    const int tid = threadIdx.x, wid = tid >> 5, lane = tid & 31;
    const int warp_m = wid >> 2, warp_n = wid & 3;
    const int bx = blockIdx.x, by = blockIdx.y;

    const __half* Ab = Ag + (size_t)(by * 128) * GK;
    const __half* Bb = Bg + (size_t)(bx * 128) * GK;

    const int pr0 = tid >> 2, pc0 = (tid & 3);
    const uint32_t aLane = (uint32_t)((lane & 15) * (LDT * 2) + (lane >> 4) * 16);
    const uint32_t bLane = (uint32_t)((((lane >> 4) & 1) * 8 + (lane & 7)) * (LDT * 2)
                                      + ((lane >> 3) & 1) * 16);

    auto prefetch = [&](int kt, int buf) {
        const uint32_t base = sb + (uint32_t)buf * BUF_B;
#pragma unroll
        for (int s = 0; s < 2; s++) {
            int row = pr0 + s * 64, ch = pc0;
            uint32_t off = (uint32_t)(row * (LDT * 2) + ch * 16);
            CP_ASYNC16(base + off,
                       (const void*)(Ab + (size_t)row * GK + kt * 32 + ch * 8));
            CP_ASYNC16(base + TILE_B + off,
                       (const void*)(Bb + (size_t)row * GK + kt * 32 + ch * 8));
        }
    };

    float acc[4][4][4];
#pragma unroll
    for (int i = 0; i < 4; i++)
#pragma unroll
        for (int j = 0; j < 4; j++)
#pragma unroll
            for (int r = 0; r < 4; r++) acc[i][j][r] = 0.f;

    prefetch(0, 0);
    CP_COMMIT();

    const int NKT = GK / 32;
    for (int kt = 0; kt < NKT; kt++) {
        const int buf = kt & 1;
        if (kt + 1 < NKT) {
            prefetch(kt + 1, buf ^ 1);
            CP_COMMIT();
            CP_WAIT(1);
        } else {
            CP_WAIT(0);
        }
        __syncthreads();

        const uint32_t abase = sb + (uint32_t)buf * BUF_B + (uint32_t)(warp_m * 64) * (LDT * 2);
        const uint32_t bbase = sb + (uint32_t)buf * BUF_B + TILE_B + (uint32_t)(warp_n * 32) * (LDT * 2);
#pragma unroll
        for (int ks = 0; ks < 2; ks++) {
            uint32_t a[4][4], b[4][2];
#pragma unroll
            for (int mt = 0; mt < 4; mt++)
                ldsm_x4(a[mt], abase + (uint32_t)(mt * 16 * LDT * 2 + ks * 32) + aLane);
#pragma unroll
            for (int np = 0; np < 2; np++) {
                uint32_t r[4];
                ldsm_x4(r, bbase + (uint32_t)(np * 16 * LDT * 2 + ks * 32) + bLane);
                b[2 * np][0] = r[0]; b[2 * np][1] = r[1];
                b[2 * np + 1][0] = r[2]; b[2 * np + 1][1] = r[3];
            }
#pragma unroll
            for (int mt = 0; mt < 4; mt++)
#pragma unroll
                for (int nt = 0; nt < 4; nt++)
                    mma16816(acc[mt][nt], a[mt], b[nt]);
        }
        __syncthreads();
    }

    const int r0 = by * 128 + warp_m * 64 + (lane >> 2);
    const int c0 = bx * 128 + warp_n * 32 + (lane & 3) * 2;
#pragma unroll
    for (int mt = 0; mt < 4; mt++)
#pragma unroll
        for (int nt = 0; nt < 4; nt++) {
            OutT* p0 = Cg + (size_t)(r0 + mt * 16) * 1024 + c0 + nt * 8;
            store2(p0, acc[mt][nt][0], acc[mt][nt][1]);
            store2(p0 + 8 * 1024, acc[mt][nt][2], acc[mt][nt][3]);
        }
}

// ===========================================================================
// FlashAttention-2 style fp16 HMMA attention.
// grid (T/128, H, B), 128 threads (4 warps); warp owns 32 q-rows.
// K-tiles of 64 keys, cp.async double-buffered K/V in smem ([key][d], 72-half
// padded rows). S and P live entirely in registers; softmax via quad shfl.
// ===========================================================================
static constexpr int ALD = 144;  // smem row stride in bytes (72 halves)

__global__ __launch_bounds__(128) void attn_mma(const __half* __restrict__ Qg,
                                                const __half* __restrict__ Kg,
                                                const __half* __restrict__ Vg,
                                                const int* __restrict__ mask,
                                                __half* __restrict__ Ctx) {
    extern __shared__ char smem[];
    const uint32_t sb = smem_u32(smem);
    const int tid = threadIdx.x, wid = tid >> 5, lane = tid & 31;
    const int qt = blockIdx.x, h = blockIdx.y, b = blockIdx.z;

    const uint32_t OFF_K = 18432, OFF_V = 36864, OFF_MK = 55296;

    const __half* Qp = Qg + ((size_t)(b * T_) + qt * 128) * HD + h * DH_;
    const __half* Kp = Kg + (size_t)(b * T_) * HD + h * DH_;
    const __half* Vp = Vg + (size_t)(b * T_) * HD + h * DH_;

    // Q tile: 128 rows x 64 halves
#pragma unroll
    for (int s = 0; s < 8; s++) {
        int slot = tid + s * 128;
        int r = slot >> 3, ch = slot & 7;
        CP_ASYNC16(sb + (uint32_t)(r * ALD + ch * 16), Qp + (size_t)r * HD + ch * 8);
    }
    auto prefetch = [&](int kt, int buf) {
#pragma unroll
        for (int s = 0; s < 4; s++) {
            int slot = tid + s * 128;
            int r = slot >> 3, ch = slot & 7;
            uint32_t off = (uint32_t)(buf * 9216 + r * ALD + ch * 16);
            const size_t g = (size_t)(kt * 64 + r) * HD + ch * 8;
            CP_ASYNC16(sb + OFF_K + off, Kp + g);
            CP_ASYNC16(sb + OFF_V + off, Vp + g);
        }
        if (tid < 64)
            CP_ASYNC4(sb + OFF_MK + (uint32_t)(buf * 256 + tid * 4),
                      mask + b * T_ + kt * 64 + tid);
    };
    prefetch(0, 0);
    CP_COMMIT();

    float mrow[2][2], lrow[2][2], o[2][8][4];
#pragma unroll
    for (int mt = 0; mt < 2; mt++) {
        mrow[mt][0] = mrow[mt][1] = -INFINITY;
        lrow[mt][0] = lrow[mt][1] = 0.f;
#pragma unroll
        for (int dd = 0; dd < 8; dd++)
#pragma unroll
            for (int r = 0; r < 4; r++) o[mt][dd][r] = 0.f;
    }

    uint32_t qa[2][4][4];
    const uint32_t aL = (uint32_t)((lane & 15) * ALD + (lane >> 4) * 16);
    const uint32_t kL = (uint32_t)((((lane >> 4) & 1) * 8 + (lane & 7)) * ALD
                                   + ((lane >> 3) & 1) * 16);
    const uint32_t vL = (uint32_t)((((lane >> 3) & 1) * 8 + (lane & 7)) * ALD
                                   + ((lane >> 4) & 1) * 16);

    const int NT = T_ / 64;
    for (int kt = 0; kt < NT; kt++) {
        const int buf = kt & 1;
        if (kt + 1 < NT) { prefetch(kt + 1, buf ^ 1); CP_COMMIT(); CP_WAIT(1); }
        else             { CP_WAIT(0); }
        __syncthreads();

        if (kt == 0) {  // Q arrived with tile 0; load A-fragments once
            const uint32_t qb = sb + (uint32_t)(wid * 32) * ALD + aL;
#pragma unroll
            for (int mt = 0; mt < 2; mt++)
#pragma unroll
                for (int ks = 0; ks < 4; ks++)
                    ldsm_x4(qa[mt][ks], qb + (uint32_t)(mt * 16 * ALD + ks * 32));
        }

        float2 bj[8];
#pragma unroll
        for (int nn = 0; nn < 8; nn++) {
            int2 mm = *(const int2*)(smem + OFF_MK + buf * 256
                                     + (nn * 8 + (lane & 3) * 2) * 4);
            bj[nn] = make_float2((mm.x - 1) * 1e9f, (mm.y - 1) * 1e9f);
        }

        // ---- S = Q K^T ----
        float s[2][8][4];
#pragma unroll
        for (int mt = 0; mt < 2; mt++)
#pragma unroll
            for (int nn = 0; nn < 8; nn++)
#pragma unroll
                for (int r = 0; r < 4; r++) s[mt][nn][r] = 0.f;

        const uint32_t kb0 = sb + OFF_K + (uint32_t)(buf * 9216) + kL;
#pragma unroll
        for (int ks = 0; ks < 4; ks++) {
            uint32_t kb[8][2];
#pragma unroll
            for (int np = 0; np < 4; np++) {
                uint32_t r[4];
                ldsm_x4(r, kb0 + (uint32_t)(np * 16 * ALD + ks * 32));
                kb[2 * np][0] = r[0]; kb[2 * np][1] = r[1];
                kb[2 * np + 1][0] = r[2]; kb[2 * np + 1][1] = r[3];
            }
#pragma unroll
            for (int mt = 0; mt < 2; mt++)
#pragma unroll
                for (int nn = 0; nn < 8; nn++)
                    mma16816(s[mt][nn], qa[mt][ks], kb[nn]);
        }

        // ---- online softmax in registers ----
#pragma unroll
        for (int mt = 0; mt < 2; mt++) {
            float mx0 = -INFINITY, mx1 = -INFINITY;
#pragma unroll
            for (int nn = 0; nn < 8; nn++) {
                s[mt][nn][0] = fmaf(s[mt][nn][0], 0.125f, bj[nn].x);
                s[mt][nn][1] = fmaf(s[mt][nn][1], 0.125f, bj[nn].y);
                s[mt][nn][2] = fmaf(s[mt][nn][2], 0.125f, bj[nn].x);
                s[mt][nn][3] = fmaf(s[mt][nn][3], 0.125f, bj[nn].y);
                mx0 = fmaxf(mx0, fmaxf(s[mt][nn][0], s[mt][nn][1]));
                mx1 = fmaxf(mx1, fmaxf(s[mt][nn][2], s[mt][nn][3]));
            }
            mx0 = fmaxf(mx0, __shfl_xor_sync(0xffffffffu, mx0, 1));
            mx0 = fmaxf(mx0, __shfl_xor_sync(0xffffffffu, mx0, 2));
            mx1 = fmaxf(mx1, __shfl_xor_sync(0xffffffffu, mx1, 1));
            mx1 = fmaxf(mx1, __shfl_xor_sync(0xffffffffu, mx1, 2));
            float nm0 = fmaxf(mrow[mt][0], mx0), nm1 = fmaxf(mrow[mt][1], mx1);
            float a0 = __expf(mrow[mt][0] - nm0), a1 = __expf(mrow[mt][1] - nm1);
            mrow[mt][0] = nm0; mrow[mt][1] = nm1;
            float p0 = 0.f, p1 = 0.f;
#pragma unroll
            for (int nn = 0; nn < 8; nn++) {
                s[mt][nn][0] = __expf(s[mt][nn][0] - nm0);
                s[mt][nn][1] = __expf(s[mt][nn][1] - nm0);
                s[mt][nn][2] = __expf(s[mt][nn][2] - nm1);
                s[mt][nn][3] = __expf(s[mt][nn][3] - nm1);
                p0 += s[mt][nn][0] + s[mt][nn][1];
                p1 += s[mt][nn][2] + s[mt][nn][3];
            }
            p0 += __shfl_xor_sync(0xffffffffu, p0, 1);
            p0 += __shfl_xor_sync(0xffffffffu, p0, 2);
            p1 += __shfl_xor_sync(0xffffffffu, p1, 1);
            p1 += __shfl_xor_sync(0xffffffffu, p1, 2);
            lrow[mt][0] = lrow[mt][0] * a0 + p0;
            lrow[mt][1] = lrow[mt][1] * a1 + p1;
#pragma unroll
            for (int dd = 0; dd < 8; dd++) {
                o[mt][dd][0] *= a0; o[mt][dd][1] *= a0;
                o[mt][dd][2] *= a1; o[mt][dd][3] *= a1;
            }
        }

        // ---- O += P V  (P from registers; V via ldmatrix.trans) ----
        const uint32_t vb0 = sb + OFF_V + (uint32_t)(buf * 9216) + vL;
#pragma unroll
        for (int kk = 0; kk < 4; kk++) {
            uint32_t pa[2][4];
#pragma unroll
            for (int mt = 0; mt < 2; mt++) {
                __half2 h0 = __floats2half2_rn(s[mt][2 * kk][0], s[mt][2 * kk][1]);
                __half2 h1 = __floats2half2_rn(s[mt][2 * kk][2], s[mt][2 * kk][3]);
                __half2 h2 = __floats2half2_rn(s[mt][2 * kk + 1][0], s[mt][2 * kk + 1][1]);
                __half2 h3 = __floats2half2_rn(s[mt][2 * kk + 1][2], s[mt][2 * kk + 1][3]);
                pa[mt][0] = *(uint32_t*)&h0; pa[mt][1] = *(uint32_t*)&h1;
                pa[mt][2] = *(uint32_t*)&h2; pa[mt][3] = *(uint32_t*)&h3;
            }
#pragma unroll
            for (int dp = 0; dp < 4; dp++) {
                uint32_t r[4];
                ldsm_x4_t(r, vb0 + (uint32_t)(kk * 16 * ALD + dp * 32));
                uint32_t v0[2] = {r[0], r[1]}, v1[2] = {r[2], r[3]};
#pragma unroll
                for (int mt = 0; mt < 2; mt++) {
                    mma16816(o[mt][2 * dp], pa[mt], v0);
                    mma16816(o[mt][2 * dp + 1], pa[mt], v1);
                }
            }
        }
        __syncthreads();
    }

    // ---- epilogue: normalize, write fp16 ctx ----
    const size_t orow = (size_t)(b * T_) + qt * 128 + wid * 32;
#pragma unroll
    for (int mt = 0; mt < 2; mt++) {
        float i0 = 1.f / lrow[mt][0], i1 = 1.f / lrow[mt][1];
        size_t r_lo = orow + mt * 16 + (lane >> 2);
        size_t r_hi = r_lo + 8;
        const int cb = h * DH_ + (lane & 3) * 2;
#pragma unroll
        for (int dd = 0; dd < 8; dd++) {
            *(__half2*)(Ctx + r_lo * HD + cb + dd * 8) =
                __floats2half2_rn(o[mt][dd][0] * i0, o[mt][dd][1] * i0);
            *(__half2*)(Ctx + r_hi * HD + cb + dd * 8) =
                __floats2half2_rn(o[mt][dd][2] * i1, o[mt][dd][3] * i1);
        }
    }
}

// ===========================================================================
// kernel_launch
// Inputs: [0]=x f32, [1]=attention_mask i32, [2]=Wq, [3]=Wk, [4]=Wv, [5]=Wo
// ===========================================================================
extern "C" void kernel_launch(void* const* d_in, const int* in_sizes, int n_in,
                              void* d_out, int out_size) {
    const float* x    = (const float*)d_in[0];
    const int*   mask = (const int*)d_in[1];
    const float* Wq   = (const float*)d_in[2];
    const float* Wk   = (const float*)d_in[3];
    const float* Wv   = (const float*)d_in[4];
    const float* Wo   = (const float*)d_in[5];
    float* out = (float*)d_out;

    __half *x16, *q16, *k16, *v16, *ctx16, *wqt, *wkt, *wvt, *wot;
    cudaGetSymbolAddress((void**)&x16, g_x16);
    cudaGetSymbolAddress((void**)&q16, g_q16);
    cudaGetSymbolAddress((void**)&k16, g_k16);
    cudaGetSymbolAddress((void**)&v16, g_v16);
    cudaGetSymbolAddress((void**)&ctx16, g_ctx16);
    cudaGetSymbolAddress((void**)&wqt, g_wqt);
    cudaGetSymbolAddress((void**)&wkt, g_wkt);
    cudaGetSymbolAddress((void**)&wvt, g_wvt);
    cudaGetSymbolAddress((void**)&wot, g_wot);

    // ---- fp16 conversions ----
    f32_to_f16_vec<<<(BT * D_ / 4) / 256, 256>>>(x, x16);
    dim3 tg(32, 32), tb(32, 8);
    transpose_f32_to_f16<<<tg, tb>>>(Wq, wqt);
    transpose_f32_to_f16<<<tg, tb>>>(Wk, wkt);
    transpose_f32_to_f16<<<tg, tb>>>(Wv, wvt);
    transpose_f32_to_f16<<<tg, tb>>>(Wo, wot);

    // ---- projections (fp16 out) ----
    dim3 gg(HD / 128, BT / 128);  // (8, 32)
    gemm_f16_mma<__half><<<gg, 256>>>(x16, wqt, q16);
    gemm_f16_mma<__half><<<gg, 256>>>(x16, wkt, k16);
    gemm_f16_mma<__half><<<gg, 256>>>(x16, wvt, v16);

    // ---- attention (fp16 HMMA, fp32 softmax) ----
    const int at_smem = 55296 + 512;  // Q+K+V tiles + mask ints
    cudaFuncSetAttribute(attn_mma, cudaFuncAttributeMaxDynamicSharedMemorySize,
                         at_smem);
    attn_mma<<<dim3(T_ / 128, H_, B_), 128, at_smem>>>(q16, k16, v16, mask, ctx16);

    // ---- output projection (fp32 out) ----
    gemm_f16_mma<float><<<gg, 256>>>(ctx16, wot, out);
}